// round 12
// baseline (speedup 1.0000x reference)
#include <cuda_runtime.h>
#include <cuda_fp16.h>

#define NN 100000
#define FD 32
#define EPT 4   // edges per scatter thread-group

// Scratch (static device globals — no allocation in kernel_launch)
__device__ __half g_sc[NN * FD];    // messages (fp16), gather side
__device__ __half g_aggh[NN * FD];  // fp16 accumulator, seeded with self-loop
__device__ float  g_dinv[NN];
__device__ int    g_deg[NN];

__global__ void k_zero() {
    int i = blockIdx.x * blockDim.x + threadIdx.x;
    if (i < NN) g_deg[i] = 1;  // self-loop contributes 1
}

__global__ void k_count(const int* __restrict__ dst, int E) {
    int t = blockIdx.x * blockDim.x + threadIdx.x;
    int e = t * 4;
    if (e + 3 < E) {
        int4 d = *reinterpret_cast<const int4*>(dst + e);
        atomicAdd(&g_deg[d.x], 1);
        atomicAdd(&g_deg[d.y], 1);
        atomicAdd(&g_deg[d.z], 1);
        atomicAdd(&g_deg[d.w], 1);
    } else {
        for (int i = e; i < E; i++) atomicAdd(&g_deg[dst[i]], 1);
    }
}

// msg0 = fp16(dinv * x); seeds fp16 accumulator (self-loop folded);
// dinv computed inline.
__global__ void k_scale0(const float* __restrict__ x) {
    int g = blockIdx.x * blockDim.x + threadIdx.x;   // one float4 per thread
    if (g >= NN * FD / 4) return;
    int node = g >> 3;
    float dv = rsqrtf((float)g_deg[node]);
    if ((g & 7) == 0) g_dinv[node] = dv;
    float4 v = *reinterpret_cast<const float4*>(x + (size_t)g * 4);
    __half2 p0 = __floats2half2_rn(v.x * dv, v.y * dv);
    __half2 p1 = __floats2half2_rn(v.z * dv, v.w * dv);
    uint2 packed;
    packed.x = *reinterpret_cast<unsigned int*>(&p0);
    packed.y = *reinterpret_cast<unsigned int*>(&p1);
    *reinterpret_cast<uint2*>(g_sc   + (size_t)g * 4) = packed;
    *reinterpret_cast<uint2*>(g_aggh + (size_t)g * 4) = packed;
}

// Scatter: 4 lanes per edge (lane covers 8 fp16 = 16B), 4 edges per thread.
// Index loads VECTORIZED: one int4 for src, one for dst (e0 is 4-aligned).
// Raw-bit uint4 gather + fp16x2 vector RED: no converts in the hot path.
__global__ __launch_bounds__(256) void k_scatter(const int* __restrict__ src,
                                                 const int* __restrict__ dst,
                                                 int E) {
    long long t = (long long)blockIdx.x * 256 + threadIdx.x;
    int e0 = (int)(t >> 2) * EPT;
    if (e0 >= E) return;
    int q = ((int)t & 3) << 3;   // feature offset 0,8,16,24 (halves)

    if (e0 + EPT <= E) {         // main path: vector index loads
        int4 s4 = *reinterpret_cast<const int4*>(src + e0);
        int4 d4 = *reinterpret_cast<const int4*>(dst + e0);

        uint4 v0 = *reinterpret_cast<const uint4*>(g_sc + (size_t)s4.x * FD + q);
        uint4 v1 = *reinterpret_cast<const uint4*>(g_sc + (size_t)s4.y * FD + q);
        uint4 v2 = *reinterpret_cast<const uint4*>(g_sc + (size_t)s4.z * FD + q);
        uint4 v3 = *reinterpret_cast<const uint4*>(g_sc + (size_t)s4.w * FD + q);

        __half* a0 = g_aggh + (size_t)d4.x * FD + q;
        __half* a1 = g_aggh + (size_t)d4.y * FD + q;
        __half* a2 = g_aggh + (size_t)d4.z * FD + q;
        __half* a3 = g_aggh + (size_t)d4.w * FD + q;
        asm volatile("red.global.add.noftz.v4.f16x2 [%0], {%1, %2, %3, %4};"
                     :: "l"(a0), "r"(v0.x), "r"(v0.y), "r"(v0.z), "r"(v0.w) : "memory");
        asm volatile("red.global.add.noftz.v4.f16x2 [%0], {%1, %2, %3, %4};"
                     :: "l"(a1), "r"(v1.x), "r"(v1.y), "r"(v1.z), "r"(v1.w) : "memory");
        asm volatile("red.global.add.noftz.v4.f16x2 [%0], {%1, %2, %3, %4};"
                     :: "l"(a2), "r"(v2.x), "r"(v2.y), "r"(v2.z), "r"(v2.w) : "memory");
        asm volatile("red.global.add.noftz.v4.f16x2 [%0], {%1, %2, %3, %4};"
                     :: "l"(a3), "r"(v3.x), "r"(v3.y), "r"(v3.z), "r"(v3.w) : "memory");
    } else {                     // tail (not hit for E=1.6M)
        for (int e = e0; e < E; e++) {
            int s = src[e];
            int d = dst[e];
            uint4 v = *reinterpret_cast<const uint4*>(g_sc + (size_t)s * FD + q);
            __half* a = g_aggh + (size_t)d * FD + q;
            asm volatile("red.global.add.noftz.v4.f16x2 [%0], {%1, %2, %3, %4};"
                         :: "l"(a), "r"(v.x), "r"(v.y), "r"(v.z), "r"(v.w) : "memory");
        }
    }
}

// Mid: ph = dinv*agg0; h1 = relu(ph @ W0 + b0); msg1 = fp16(dinv*h1).
__global__ __launch_bounds__(256) void k_mid(const float* __restrict__ W0,
                                             const float* __restrict__ b0) {
    __shared__ float Ws[FD * FD];
    __shared__ float s_row[8][FD];
    int tid = threadIdx.x;
    int lane = tid & 31;
    int wb = tid >> 5;
    #pragma unroll
    for (int i = tid; i < FD * FD; i += 256) Ws[i] = W0[i];
    __syncthreads();

    float Wc[FD];
    #pragma unroll
    for (int k = 0; k < FD; k++) Wc[k] = Ws[k * FD + lane];
    float bl = b0[lane];

    int base = (blockIdx.x * 8 + wb) * 8;    // 8 nodes per warp
    if (base >= NN) return;

    __half vh[8];
    float dvv[8];
    #pragma unroll
    for (int u = 0; u < 8; u++) {            // batched loads, MLP=8
        vh[u]  = g_aggh[(size_t)(base + u) * FD + lane];
        dvv[u] = __ldg(&g_dinv[base + u]);
    }

    #pragma unroll
    for (int u = 0; u < 8; u++) {
        int node = base + u;
        s_row[wb][lane] = dvv[u] * __half2float(vh[u]);
        __syncwarp();
        const float4* r = reinterpret_cast<const float4*>(s_row[wb]);
        float acc = 0.0f;
        #pragma unroll
        for (int j = 0; j < FD / 4; j++) {
            float4 t4 = r[j];                // broadcast LDS.128
            acc = fmaf(t4.x, Wc[4 * j + 0], acc);
            acc = fmaf(t4.y, Wc[4 * j + 1], acc);
            acc = fmaf(t4.z, Wc[4 * j + 2], acc);
            acc = fmaf(t4.w, Wc[4 * j + 3], acc);
        }
        __syncwarp();
        __half s1 = __float2half(dvv[u] * fmaxf(acc + bl, 0.0f));
        g_sc[(size_t)node * FD + lane]   = s1;
        g_aggh[(size_t)node * FD + lane] = s1;
    }
}

// Final: ph = dinv*agg1; h2 = relu(ph @ W1 + b1); out = h2 @ Wf + bf.
__global__ __launch_bounds__(256) void k_final(const float* __restrict__ W1,
                                               const float* __restrict__ b1,
                                               const float* __restrict__ Wf,
                                               const float* __restrict__ bf,
                                               float* __restrict__ out) {
    __shared__ float Ws1[FD * FD];
    __shared__ float Wsf[FD * FD];
    __shared__ float s_row[8][FD];
    int tid = threadIdx.x;
    int lane = tid & 31;
    int wb = tid >> 5;
    #pragma unroll
    for (int i = tid; i < FD * FD; i += 256) { Ws1[i] = W1[i]; Wsf[i] = Wf[i]; }
    __syncthreads();

    float Wc1[FD];
    #pragma unroll
    for (int k = 0; k < FD; k++) Wc1[k] = Ws1[k * FD + lane];
    float b1l = b1[lane];
    float bfl = bf[lane];

    int base = (blockIdx.x * 8 + wb) * 8;
    if (base >= NN) return;

    __half vh[8];
    float dvv[8];
    #pragma unroll
    for (int u = 0; u < 8; u++) {
        vh[u]  = g_aggh[(size_t)(base + u) * FD + lane];
        dvv[u] = __ldg(&g_dinv[base + u]);
    }

    #pragma unroll
    for (int u = 0; u < 8; u++) {
        int node = base + u;
        s_row[wb][lane] = dvv[u] * __half2float(vh[u]);
        __syncwarp();
        const float4* r = reinterpret_cast<const float4*>(s_row[wb]);
        float o1 = 0.0f;
        #pragma unroll
        for (int j = 0; j < FD / 4; j++) {
            float4 t4 = r[j];
            o1 = fmaf(t4.x, Wc1[4 * j + 0], o1);
            o1 = fmaf(t4.y, Wc1[4 * j + 1], o1);
            o1 = fmaf(t4.z, Wc1[4 * j + 2], o1);
            o1 = fmaf(t4.w, Wc1[4 * j + 3], o1);
        }
        __syncwarp();
        float h2 = fmaxf(o1 + b1l, 0.0f);
        s_row[wb][lane] = h2;
        __syncwarp();
        float o2 = bfl;
        #pragma unroll
        for (int j = 0; j < FD / 4; j++) {
            float4 t4 = r[j];
            o2 = fmaf(t4.x, Wsf[(4 * j + 0) * FD + lane], o2);
            o2 = fmaf(t4.y, Wsf[(4 * j + 1) * FD + lane], o2);
            o2 = fmaf(t4.z, Wsf[(4 * j + 2) * FD + lane], o2);
            o2 = fmaf(t4.w, Wsf[(4 * j + 3) * FD + lane], o2);
        }
        __syncwarp();
        out[(size_t)node * FD + lane] = o2;
    }
}

extern "C" void kernel_launch(void* const* d_in, const int* in_sizes, int n_in,
                              void* d_out, int out_size) {
    const float* x   = (const float*)d_in[0];
    const int*   ei  = (const int*)d_in[1];   // JAX x64 disabled -> int32
    const float* W0  = (const float*)d_in[2];
    const float* b0  = (const float*)d_in[3];
    const float* W1  = (const float*)d_in[4];
    const float* b1  = (const float*)d_in[5];
    const float* Wf  = (const float*)d_in[6];
    const float* bf  = (const float*)d_in[7];
    float* out = (float*)d_out;

    int E = in_sizes[1] / 2;          // edge_index is [2, E]
    const int* src = ei;
    const int* dst = ei + E;

    int nb_n  = (NN + 255) / 256;
    int nb_c  = ((E + 3) / 4 + 255) / 256;
    int nb_s0 = (NN * FD / 4 + 255) / 256;
    int nb_x  = (NN / 8 + 7) / 8;                // 1563 blocks (8 warps each)
    long long sthreads = (long long)((E + EPT - 1) / EPT) * 4;
    int nb_s  = (int)((sthreads + 255) / 256);

    // degree + normalization (dinv fused into scale0)
    k_zero<<<nb_n, 256>>>();
    k_count<<<nb_c, 256>>>(dst, E);

    // layer 0: scale only (W0 applied after aggregation)
    k_scale0<<<nb_s0, 256>>>(x);
    k_scatter<<<nb_s, 256>>>(src, dst, E);

    // mid: apply W0 + relu, produce layer-1 messages
    k_mid<<<nb_x, 256>>>(W0, b0);
    k_scatter<<<nb_s, 256>>>(src, dst, E);

    // final: apply W1 + relu, then Wf + bf
    k_final<<<nb_x, 256>>>(W1, b1, Wf, bf, out);
}

// round 13
// speedup vs baseline: 1.0890x; 1.0890x over previous
#include <cuda_runtime.h>
#include <cuda_fp16.h>

#define NN 100000
#define FD 32
#define EPT 4   // edges per scatter thread-group

// Scratch (static device globals — no allocation in kernel_launch)
__device__ __half g_sc[NN * FD];    // messages (fp16), gather side
__device__ __half g_aggh[NN * FD];  // fp16 accumulator, seeded with self-loop
__device__ float  g_dinv[NN];
__device__ int    g_deg[NN];

__global__ void k_zero() {
    int i = blockIdx.x * blockDim.x + threadIdx.x;
    if (i < NN) g_deg[i] = 1;  // self-loop contributes 1
}

__global__ void k_count(const int* __restrict__ dst, int E) {
    int t = blockIdx.x * blockDim.x + threadIdx.x;
    int e = t * 4;
    if (e + 3 < E) {
        int4 d = *reinterpret_cast<const int4*>(dst + e);
        atomicAdd(&g_deg[d.x], 1);
        atomicAdd(&g_deg[d.y], 1);
        atomicAdd(&g_deg[d.z], 1);
        atomicAdd(&g_deg[d.w], 1);
    } else {
        for (int i = e; i < E; i++) atomicAdd(&g_deg[dst[i]], 1);
    }
}

// msg0 = fp16(dinv * x); seeds fp16 accumulator (self-loop folded);
// dinv computed inline.
__global__ void k_scale0(const float* __restrict__ x) {
    int g = blockIdx.x * blockDim.x + threadIdx.x;   // one float4 per thread
    if (g >= NN * FD / 4) return;
    int node = g >> 3;
    float dv = rsqrtf((float)g_deg[node]);
    if ((g & 7) == 0) g_dinv[node] = dv;
    float4 v = *reinterpret_cast<const float4*>(x + (size_t)g * 4);
    __half2 p0 = __floats2half2_rn(v.x * dv, v.y * dv);
    __half2 p1 = __floats2half2_rn(v.z * dv, v.w * dv);
    uint2 packed;
    packed.x = *reinterpret_cast<unsigned int*>(&p0);
    packed.y = *reinterpret_cast<unsigned int*>(&p1);
    *reinterpret_cast<uint2*>(g_sc   + (size_t)g * 4) = packed;
    *reinterpret_cast<uint2*>(g_aggh + (size_t)g * 4) = packed;
}

// Scatter: 4 lanes per edge (lane covers 8 fp16 = 16B), 4 edges per thread.
// Raw-bit uint4 gather + fp16x2 vector RED: no converts in the hot path.
// At the RED-wavefront wall (~26.7us) — structurally minimal.
__global__ __launch_bounds__(256) void k_scatter(const int* __restrict__ src,
                                                 const int* __restrict__ dst,
                                                 int E) {
    long long t = (long long)blockIdx.x * 256 + threadIdx.x;
    int e0 = (int)(t >> 2) * EPT;
    if (e0 >= E) return;
    int q = ((int)t & 3) << 3;   // feature offset 0,8,16,24 (halves)

    if (e0 + EPT <= E) {
        int4 s4 = *reinterpret_cast<const int4*>(src + e0);
        int4 d4 = *reinterpret_cast<const int4*>(dst + e0);

        uint4 v0 = *reinterpret_cast<const uint4*>(g_sc + (size_t)s4.x * FD + q);
        uint4 v1 = *reinterpret_cast<const uint4*>(g_sc + (size_t)s4.y * FD + q);
        uint4 v2 = *reinterpret_cast<const uint4*>(g_sc + (size_t)s4.z * FD + q);
        uint4 v3 = *reinterpret_cast<const uint4*>(g_sc + (size_t)s4.w * FD + q);

        __half* a0 = g_aggh + (size_t)d4.x * FD + q;
        __half* a1 = g_aggh + (size_t)d4.y * FD + q;
        __half* a2 = g_aggh + (size_t)d4.z * FD + q;
        __half* a3 = g_aggh + (size_t)d4.w * FD + q;
        asm volatile("red.global.add.noftz.v4.f16x2 [%0], {%1, %2, %3, %4};"
                     :: "l"(a0), "r"(v0.x), "r"(v0.y), "r"(v0.z), "r"(v0.w) : "memory");
        asm volatile("red.global.add.noftz.v4.f16x2 [%0], {%1, %2, %3, %4};"
                     :: "l"(a1), "r"(v1.x), "r"(v1.y), "r"(v1.z), "r"(v1.w) : "memory");
        asm volatile("red.global.add.noftz.v4.f16x2 [%0], {%1, %2, %3, %4};"
                     :: "l"(a2), "r"(v2.x), "r"(v2.y), "r"(v2.z), "r"(v2.w) : "memory");
        asm volatile("red.global.add.noftz.v4.f16x2 [%0], {%1, %2, %3, %4};"
                     :: "l"(a3), "r"(v3.x), "r"(v3.y), "r"(v3.z), "r"(v3.w) : "memory");
    } else {
        for (int e = e0; e < E; e++) {
            int s = src[e];
            int d = dst[e];
            uint4 v = *reinterpret_cast<const uint4*>(g_sc + (size_t)s * FD + q);
            __half* a = g_aggh + (size_t)d * FD + q;
            asm volatile("red.global.add.noftz.v4.f16x2 [%0], {%1, %2, %3, %4};"
                         :: "l"(a), "r"(v.x), "r"(v.y), "r"(v.z), "r"(v.w) : "memory");
        }
    }
}

// Mid: ph = dinv*agg0; h1 = relu(ph @ W0 + b0); msg1 = fp16(dinv*h1).
// ILP version: stage all 8 node-rows, ONE syncwarp, then 8 interleaved GEMVs.
__global__ __launch_bounds__(256) void k_mid(const float* __restrict__ W0,
                                             const float* __restrict__ b0) {
    __shared__ float Ws[FD * FD];
    __shared__ float s_row[8][8][FD];   // [warp][node][feature], 8KB
    int tid = threadIdx.x;
    int lane = tid & 31;
    int wb = tid >> 5;
    #pragma unroll
    for (int i = tid; i < FD * FD; i += 256) Ws[i] = W0[i];
    __syncthreads();

    float Wc[FD];
    #pragma unroll
    for (int k = 0; k < FD; k++) Wc[k] = Ws[k * FD + lane];
    float bl = b0[lane];

    int base = (blockIdx.x * 8 + wb) * 8;    // 8 nodes per warp
    if (base >= NN) return;

    __half vh[8];
    float dvv[8];
    #pragma unroll
    for (int u = 0; u < 8; u++) {            // batched loads, MLP=8
        vh[u]  = g_aggh[(size_t)(base + u) * FD + lane];
        dvv[u] = __ldg(&g_dinv[base + u]);
    }
    #pragma unroll
    for (int u = 0; u < 8; u++)
        s_row[wb][u][lane] = dvv[u] * __half2float(vh[u]);
    __syncwarp();

    float acc[8] = {0, 0, 0, 0, 0, 0, 0, 0};
    #pragma unroll
    for (int j = 0; j < FD / 4; j++) {       // j-outer: Wc reuse, 8-way ILP
        #pragma unroll
        for (int u = 0; u < 8; u++) {
            float4 t4 = *reinterpret_cast<const float4*>(&s_row[wb][u][4 * j]);
            acc[u] = fmaf(t4.x, Wc[4 * j + 0], acc[u]);
            acc[u] = fmaf(t4.y, Wc[4 * j + 1], acc[u]);
            acc[u] = fmaf(t4.z, Wc[4 * j + 2], acc[u]);
            acc[u] = fmaf(t4.w, Wc[4 * j + 3], acc[u]);
        }
    }
    #pragma unroll
    for (int u = 0; u < 8; u++) {
        int node = base + u;
        __half s1 = __float2half(dvv[u] * fmaxf(acc[u] + bl, 0.0f));
        g_sc[(size_t)node * FD + lane]   = s1;
        g_aggh[(size_t)node * FD + lane] = s1;
    }
}

// Final: ph = dinv*agg1; h2 = relu(ph @ W1 + b1); out = h2 @ Wf + bf.
// Same ILP structure, two sequential GEMV stages (register reuse for W cols).
__global__ __launch_bounds__(256) void k_final(const float* __restrict__ W1,
                                               const float* __restrict__ b1,
                                               const float* __restrict__ Wf,
                                               const float* __restrict__ bf,
                                               float* __restrict__ out) {
    __shared__ float Ws1[FD * FD];
    __shared__ float Wsf[FD * FD];
    __shared__ float s_row[8][8][FD];
    int tid = threadIdx.x;
    int lane = tid & 31;
    int wb = tid >> 5;
    #pragma unroll
    for (int i = tid; i < FD * FD; i += 256) { Ws1[i] = W1[i]; Wsf[i] = Wf[i]; }
    __syncthreads();

    float b1l = b1[lane];
    float bfl = bf[lane];

    int base = (blockIdx.x * 8 + wb) * 8;
    if (base >= NN) return;

    __half vh[8];
    float dvv[8];
    #pragma unroll
    for (int u = 0; u < 8; u++) {
        vh[u]  = g_aggh[(size_t)(base + u) * FD + lane];
        dvv[u] = __ldg(&g_dinv[base + u]);
    }
    #pragma unroll
    for (int u = 0; u < 8; u++)
        s_row[wb][u][lane] = dvv[u] * __half2float(vh[u]);
    __syncwarp();

    // Stage 1: h2 = relu(ph @ W1 + b1)
    {
        float Wc[FD];
        #pragma unroll
        for (int k = 0; k < FD; k++) Wc[k] = Ws1[k * FD + lane];
        float acc[8] = {0, 0, 0, 0, 0, 0, 0, 0};
        #pragma unroll
        for (int j = 0; j < FD / 4; j++) {
            #pragma unroll
            for (int u = 0; u < 8; u++) {
                float4 t4 = *reinterpret_cast<const float4*>(&s_row[wb][u][4 * j]);
                acc[u] = fmaf(t4.x, Wc[4 * j + 0], acc[u]);
                acc[u] = fmaf(t4.y, Wc[4 * j + 1], acc[u]);
                acc[u] = fmaf(t4.z, Wc[4 * j + 2], acc[u]);
                acc[u] = fmaf(t4.w, Wc[4 * j + 3], acc[u]);
            }
        }
        __syncwarp();                        // all reads of s_row done
        #pragma unroll
        for (int u = 0; u < 8; u++)
            s_row[wb][u][lane] = fmaxf(acc[u] + b1l, 0.0f);
        __syncwarp();
    }

    // Stage 2: out = h2 @ Wf + bf
    {
        float Wc[FD];
        #pragma unroll
        for (int k = 0; k < FD; k++) Wc[k] = Wsf[k * FD + lane];
        float acc[8];
        #pragma unroll
        for (int u = 0; u < 8; u++) acc[u] = bfl;
        #pragma unroll
        for (int j = 0; j < FD / 4; j++) {
            #pragma unroll
            for (int u = 0; u < 8; u++) {
                float4 t4 = *reinterpret_cast<const float4*>(&s_row[wb][u][4 * j]);
                acc[u] = fmaf(t4.x, Wc[4 * j + 0], acc[u]);
                acc[u] = fmaf(t4.y, Wc[4 * j + 1], acc[u]);
                acc[u] = fmaf(t4.z, Wc[4 * j + 2], acc[u]);
                acc[u] = fmaf(t4.w, Wc[4 * j + 3], acc[u]);
            }
        }
        #pragma unroll
        for (int u = 0; u < 8; u++)
            out[(size_t)(base + u) * FD + lane] = acc[u];
    }
}

extern "C" void kernel_launch(void* const* d_in, const int* in_sizes, int n_in,
                              void* d_out, int out_size) {
    const float* x   = (const float*)d_in[0];
    const int*   ei  = (const int*)d_in[1];   // JAX x64 disabled -> int32
    const float* W0  = (const float*)d_in[2];
    const float* b0  = (const float*)d_in[3];
    const float* W1  = (const float*)d_in[4];
    const float* b1  = (const float*)d_in[5];
    const float* Wf  = (const float*)d_in[6];
    const float* bf  = (const float*)d_in[7];
    float* out = (float*)d_out;

    int E = in_sizes[1] / 2;          // edge_index is [2, E]
    const int* src = ei;
    const int* dst = ei + E;

    int nb_n  = (NN + 255) / 256;
    int nb_c  = ((E + 3) / 4 + 255) / 256;
    int nb_s0 = (NN * FD / 4 + 255) / 256;
    int nb_x  = (NN / 8 + 7) / 8;                // 1563 blocks (8 warps each)
    long long sthreads = (long long)((E + EPT - 1) / EPT) * 4;
    int nb_s  = (int)((sthreads + 255) / 256);

    // degree + normalization (dinv fused into scale0)
    k_zero<<<nb_n, 256>>>();
    k_count<<<nb_c, 256>>>(dst, E);

    // layer 0: scale only (W0 applied after aggregation)
    k_scale0<<<nb_s0, 256>>>(x);
    k_scatter<<<nb_s, 256>>>(src, dst, E);

    // mid: apply W0 + relu, produce layer-1 messages
    k_mid<<<nb_x, 256>>>(W0, b0);
    k_scatter<<<nb_s, 256>>>(src, dst, E);

    // final: apply W1 + relu, then Wf + bf
    k_final<<<nb_x, 256>>>(W1, b1, Wf, bf, out);
}

// round 14
// speedup vs baseline: 1.1323x; 1.0397x over previous
#include <cuda_runtime.h>
#include <cuda_fp16.h>

#define NN 100000
#define FD 32
#define EPT 4   // edges per scatter thread-group

// Scratch (static device globals — no allocation in kernel_launch)
__device__ __half g_sc[NN * FD];    // messages (fp16), gather side
__device__ __half g_aggh[NN * FD];  // fp16 accumulator, seeded with self-loop
__device__ float  g_dinv[NN];
__device__ int    g_deg[NN];

__global__ void k_zero() {
    cudaTriggerProgrammaticLaunchCompletion();
    int i = blockIdx.x * blockDim.x + threadIdx.x;
    if (i < NN) g_deg[i] = 1;  // self-loop contributes 1
}

__global__ void k_count(const int* __restrict__ dst, int E) {
    cudaTriggerProgrammaticLaunchCompletion();
    int t = blockIdx.x * blockDim.x + threadIdx.x;
    int e = t * 4;
    if (e + 3 < E) {
        int4 d = *reinterpret_cast<const int4*>(dst + e);   // input-only, early
        cudaGridDependencySynchronize();                     // wait k_zero
        atomicAdd(&g_deg[d.x], 1);
        atomicAdd(&g_deg[d.y], 1);
        atomicAdd(&g_deg[d.z], 1);
        atomicAdd(&g_deg[d.w], 1);
    } else {
        cudaGridDependencySynchronize();
        for (int i = e; i < E; i++) atomicAdd(&g_deg[dst[i]], 1);
    }
}

// msg0 = fp16(dinv * x); seeds fp16 accumulator (self-loop folded);
// dinv computed inline from deg.
__global__ void k_scale0(const float* __restrict__ x) {
    cudaTriggerProgrammaticLaunchCompletion();
    int g = blockIdx.x * blockDim.x + threadIdx.x;   // one float4 per thread
    if (g >= NN * FD / 4) return;
    float4 v = *reinterpret_cast<const float4*>(x + (size_t)g * 4);  // input, early
    cudaGridDependencySynchronize();                  // wait k_count (deg final)
    int node = g >> 3;
    float dv = rsqrtf((float)g_deg[node]);
    if ((g & 7) == 0) g_dinv[node] = dv;
    __half2 p0 = __floats2half2_rn(v.x * dv, v.y * dv);
    __half2 p1 = __floats2half2_rn(v.z * dv, v.w * dv);
    uint2 packed;
    packed.x = *reinterpret_cast<unsigned int*>(&p0);
    packed.y = *reinterpret_cast<unsigned int*>(&p1);
    *reinterpret_cast<uint2*>(g_sc   + (size_t)g * 4) = packed;
    *reinterpret_cast<uint2*>(g_aggh + (size_t)g * 4) = packed;
}

// Scatter: 4 lanes per edge (lane covers 8 fp16 = 16B), 4 edges per thread.
// Raw-bit uint4 gather + fp16x2 vector RED. Index loads issued before the
// grid-dependency sync (inputs only).
__global__ __launch_bounds__(256) void k_scatter(const int* __restrict__ src,
                                                 const int* __restrict__ dst,
                                                 int E) {
    cudaTriggerProgrammaticLaunchCompletion();
    long long t = (long long)blockIdx.x * 256 + threadIdx.x;
    int e0 = (int)(t >> 2) * EPT;
    if (e0 >= E) return;
    int q = ((int)t & 3) << 3;   // feature offset 0,8,16,24 (halves)

    if (e0 + EPT <= E) {
        int4 s4 = *reinterpret_cast<const int4*>(src + e0);  // input, early
        int4 d4 = *reinterpret_cast<const int4*>(dst + e0);
        cudaGridDependencySynchronize();                      // wait producer

        uint4 v0 = *reinterpret_cast<const uint4*>(g_sc + (size_t)s4.x * FD + q);
        uint4 v1 = *reinterpret_cast<const uint4*>(g_sc + (size_t)s4.y * FD + q);
        uint4 v2 = *reinterpret_cast<const uint4*>(g_sc + (size_t)s4.z * FD + q);
        uint4 v3 = *reinterpret_cast<const uint4*>(g_sc + (size_t)s4.w * FD + q);

        __half* a0 = g_aggh + (size_t)d4.x * FD + q;
        __half* a1 = g_aggh + (size_t)d4.y * FD + q;
        __half* a2 = g_aggh + (size_t)d4.z * FD + q;
        __half* a3 = g_aggh + (size_t)d4.w * FD + q;
        asm volatile("red.global.add.noftz.v4.f16x2 [%0], {%1, %2, %3, %4};"
                     :: "l"(a0), "r"(v0.x), "r"(v0.y), "r"(v0.z), "r"(v0.w) : "memory");
        asm volatile("red.global.add.noftz.v4.f16x2 [%0], {%1, %2, %3, %4};"
                     :: "l"(a1), "r"(v1.x), "r"(v1.y), "r"(v1.z), "r"(v1.w) : "memory");
        asm volatile("red.global.add.noftz.v4.f16x2 [%0], {%1, %2, %3, %4};"
                     :: "l"(a2), "r"(v2.x), "r"(v2.y), "r"(v2.z), "r"(v2.w) : "memory");
        asm volatile("red.global.add.noftz.v4.f16x2 [%0], {%1, %2, %3, %4};"
                     :: "l"(a3), "r"(v3.x), "r"(v3.y), "r"(v3.z), "r"(v3.w) : "memory");
    } else {
        cudaGridDependencySynchronize();
        for (int e = e0; e < E; e++) {
            int s = src[e];
            int d = dst[e];
            uint4 v = *reinterpret_cast<const uint4*>(g_sc + (size_t)s * FD + q);
            __half* a = g_aggh + (size_t)d * FD + q;
            asm volatile("red.global.add.noftz.v4.f16x2 [%0], {%1, %2, %3, %4};"
                         :: "l"(a), "r"(v.x), "r"(v.y), "r"(v.z), "r"(v.w) : "memory");
        }
    }
}

// Mid: ph = dinv*agg0; h1 = relu(ph @ W0 + b0); msg1 = fp16(dinv*h1).
// W staging before sync (pure input); dinv/agg reads after (may predate
// scale0 completion in a PDL chain otherwise).
__global__ __launch_bounds__(256) void k_mid(const float* __restrict__ W0,
                                             const float* __restrict__ b0) {
    cudaTriggerProgrammaticLaunchCompletion();
    __shared__ float Ws[FD * FD];
    __shared__ float s_row[8][8][FD];   // [warp][node][feature], 8KB
    int tid = threadIdx.x;
    int lane = tid & 31;
    int wb = tid >> 5;
    #pragma unroll
    for (int i = tid; i < FD * FD; i += 256) Ws[i] = W0[i];  // input, early
    float bl = b0[lane];
    __syncthreads();

    float Wc[FD];
    #pragma unroll
    for (int k = 0; k < FD; k++) Wc[k] = Ws[k * FD + lane];

    int base = (blockIdx.x * 8 + wb) * 8;    // 8 nodes per warp
    if (base >= NN) return;

    cudaGridDependencySynchronize();         // wait scatter1 (implies scale0 done)

    __half vh[8];
    float dvv[8];
    #pragma unroll
    for (int u = 0; u < 8; u++) {            // batched loads, MLP=8
        vh[u]  = g_aggh[(size_t)(base + u) * FD + lane];
        dvv[u] = __ldg(&g_dinv[base + u]);
    }
    #pragma unroll
    for (int u = 0; u < 8; u++)
        s_row[wb][u][lane] = dvv[u] * __half2float(vh[u]);
    __syncwarp();

    float acc[8] = {0, 0, 0, 0, 0, 0, 0, 0};
    #pragma unroll
    for (int j = 0; j < FD / 4; j++) {       // j-outer: Wc reuse, 8-way ILP
        #pragma unroll
        for (int u = 0; u < 8; u++) {
            float4 t4 = *reinterpret_cast<const float4*>(&s_row[wb][u][4 * j]);
            acc[u] = fmaf(t4.x, Wc[4 * j + 0], acc[u]);
            acc[u] = fmaf(t4.y, Wc[4 * j + 1], acc[u]);
            acc[u] = fmaf(t4.z, Wc[4 * j + 2], acc[u]);
            acc[u] = fmaf(t4.w, Wc[4 * j + 3], acc[u]);
        }
    }
    #pragma unroll
    for (int u = 0; u < 8; u++) {
        int node = base + u;
        __half s1 = __float2half(dvv[u] * fmaxf(acc[u] + bl, 0.0f));
        g_sc[(size_t)node * FD + lane]   = s1;
        g_aggh[(size_t)node * FD + lane] = s1;
    }
}

// Final: ph = dinv*agg1; h2 = relu(ph @ W1 + b1); out = h2 @ Wf + bf.
__global__ __launch_bounds__(256) void k_final(const float* __restrict__ W1,
                                               const float* __restrict__ b1,
                                               const float* __restrict__ Wf,
                                               const float* __restrict__ bf,
                                               float* __restrict__ out) {
    cudaTriggerProgrammaticLaunchCompletion();
    __shared__ float Ws1[FD * FD];
    __shared__ float Wsf[FD * FD];
    __shared__ float s_row[8][8][FD];
    int tid = threadIdx.x;
    int lane = tid & 31;
    int wb = tid >> 5;
    #pragma unroll
    for (int i = tid; i < FD * FD; i += 256) { Ws1[i] = W1[i]; Wsf[i] = Wf[i]; }
    float b1l = b1[lane];
    float bfl = bf[lane];
    __syncthreads();

    int base = (blockIdx.x * 8 + wb) * 8;
    if (base >= NN) return;

    cudaGridDependencySynchronize();         // wait scatter2

    __half vh[8];
    float dvv[8];
    #pragma unroll
    for (int u = 0; u < 8; u++) {
        vh[u]  = g_aggh[(size_t)(base + u) * FD + lane];
        dvv[u] = __ldg(&g_dinv[base + u]);
    }
    #pragma unroll
    for (int u = 0; u < 8; u++)
        s_row[wb][u][lane] = dvv[u] * __half2float(vh[u]);
    __syncwarp();

    // Stage 1: h2 = relu(ph @ W1 + b1)
    {
        float Wc[FD];
        #pragma unroll
        for (int k = 0; k < FD; k++) Wc[k] = Ws1[k * FD + lane];
        float acc[8] = {0, 0, 0, 0, 0, 0, 0, 0};
        #pragma unroll
        for (int j = 0; j < FD / 4; j++) {
            #pragma unroll
            for (int u = 0; u < 8; u++) {
                float4 t4 = *reinterpret_cast<const float4*>(&s_row[wb][u][4 * j]);
                acc[u] = fmaf(t4.x, Wc[4 * j + 0], acc[u]);
                acc[u] = fmaf(t4.y, Wc[4 * j + 1], acc[u]);
                acc[u] = fmaf(t4.z, Wc[4 * j + 2], acc[u]);
                acc[u] = fmaf(t4.w, Wc[4 * j + 3], acc[u]);
            }
        }
        __syncwarp();                        // all reads of s_row done
        #pragma unroll
        for (int u = 0; u < 8; u++)
            s_row[wb][u][lane] = fmaxf(acc[u] + b1l, 0.0f);
        __syncwarp();
    }

    // Stage 2: out = h2 @ Wf + bf
    {
        float Wc[FD];
        #pragma unroll
        for (int k = 0; k < FD; k++) Wc[k] = Wsf[k * FD + lane];
        float acc[8];
        #pragma unroll
        for (int u = 0; u < 8; u++) acc[u] = bfl;
        #pragma unroll
        for (int j = 0; j < FD / 4; j++) {
            #pragma unroll
            for (int u = 0; u < 8; u++) {
                float4 t4 = *reinterpret_cast<const float4*>(&s_row[wb][u][4 * j]);
                acc[u] = fmaf(t4.x, Wc[4 * j + 0], acc[u]);
                acc[u] = fmaf(t4.y, Wc[4 * j + 1], acc[u]);
                acc[u] = fmaf(t4.z, Wc[4 * j + 2], acc[u]);
                acc[u] = fmaf(t4.w, Wc[4 * j + 3], acc[u]);
            }
        }
        #pragma unroll
        for (int u = 0; u < 8; u++)
            out[(size_t)(base + u) * FD + lane] = acc[u];
    }
}

extern "C" void kernel_launch(void* const* d_in, const int* in_sizes, int n_in,
                              void* d_out, int out_size) {
    const float* x   = (const float*)d_in[0];
    const int*   ei  = (const int*)d_in[1];   // JAX x64 disabled -> int32
    const float* W0  = (const float*)d_in[2];
    const float* b0  = (const float*)d_in[3];
    const float* W1  = (const float*)d_in[4];
    const float* b1  = (const float*)d_in[5];
    const float* Wf  = (const float*)d_in[6];
    const float* bf  = (const float*)d_in[7];
    float* out = (float*)d_out;

    int E = in_sizes[1] / 2;          // edge_index is [2, E]
    const int* src = ei;
    const int* dst = ei + E;

    int nb_n  = (NN + 255) / 256;
    int nb_c  = ((E + 3) / 4 + 255) / 256;
    int nb_s0 = (NN * FD / 4 + 255) / 256;
    int nb_x  = (NN / 8 + 7) / 8;                // 1563 blocks (8 warps each)
    long long sthreads = (long long)((E + EPT - 1) / EPT) * 4;
    int nb_s  = (int)((sthreads + 255) / 256);

    // PDL launch config: allow each kernel to launch while its predecessor
    // is still draining; device-side cudaGridDependencySynchronize() guards
    // the actual data dependencies.
    cudaLaunchConfig_t cfg = {};
    cudaLaunchAttribute at[1];
    at[0].id = cudaLaunchAttributeProgrammaticStreamSerialization;
    at[0].val.programmaticStreamSerializationAllowed = 1;
    cfg.attrs = at;
    cfg.numAttrs = 1;
    cfg.blockDim = dim3(256, 1, 1);
    cfg.stream = 0;

    cfg.gridDim = dim3(nb_n, 1, 1);
    cudaLaunchKernelEx(&cfg, k_zero);

    cfg.gridDim = dim3(nb_c, 1, 1);
    cudaLaunchKernelEx(&cfg, k_count, dst, E);

    cfg.gridDim = dim3(nb_s0, 1, 1);
    cudaLaunchKernelEx(&cfg, k_scale0, x);

    cfg.gridDim = dim3(nb_s, 1, 1);
    cudaLaunchKernelEx(&cfg, k_scatter, src, dst, E);

    cfg.gridDim = dim3(nb_x, 1, 1);
    cudaLaunchKernelEx(&cfg, k_mid, W0, b0);

    cfg.gridDim = dim3(nb_s, 1, 1);
    cudaLaunchKernelEx(&cfg, k_scatter, src, dst, E);

    cfg.gridDim = dim3(nb_x, 1, 1);
    cudaLaunchKernelEx(&cfg, k_final, W1, b1, Wf, bf, out);
}